// round 11
// baseline (speedup 1.0000x reference)
#include <cuda_runtime.h>

#define NU 96
#define IMG 32
#define SHAPE 3072                 // NU*IMG
#define NUNITS 9216                // NU*NU
#define NELEM (SHAPE * SHAPE)
#define ZBLK 768                   // SHAPE/4 rows-per-block

// Scratch (no allocations). g_z zero-init at load; re-zeroed by the k_z tail
// every launch -> stateless across graph replays.
__device__ float g_z[NUNITS];
__device__ float g_fm[NUNITS];
__device__ float g_va[NUNITS];
__device__ unsigned g_count;

// ---------------------------------------------------------------------------
// k_z: block = 4 full rows (2 contiguous 48KB streams). Warp = half-row.
// Each float4 belongs to one tile; 8-lane groups cover one tile's 32B span.
// Partial z per (row, tile) -> SMEM -> one atomicAdd per tile per block.
// Last block: argmin + BMU scalars + fm/va tables + rad/lr outputs + reset.
// ---------------------------------------------------------------------------
__global__ void __launch_bounds__(256) k_z(const float* __restrict__ som,
                                           const float* __restrict__ var,
                                           const float* __restrict__ x,
                                           const float* __restrict__ radius,
                                           const float* __restrict__ lrr,
                                           const float* __restrict__ bmu_count,
                                           float* __restrict__ out_rad,
                                           float* __restrict__ out_lr) {
    __shared__ float4 sx[32];              // 4 rows x 8 float4 of x
    __shared__ float s_part[4][96];
    const int t = threadIdx.x;
    const int w = t >> 5, lane = t & 31;
    const int lrow = w >> 1, h = w & 1;    // local row 0..3, half 0/1
    const int rbase = blockIdx.x * 4;
    const int r = rbase + lrow;

    if (t < 32)
        sx[t] = ((const float4*)x)[((rbase & 31) + (t >> 3)) * 8 + (t & 7)];
    __syncthreads();

    const float4* srow = (const float4*)(som + (size_t)r * SHAPE);
    const float4* vrow = (const float4*)(var + (size_t)r * SHAPE);
    const float4 xq = sx[(lrow << 3) | (lane & 7)];
    const int base4 = h * 384 + lane;      // float4 index within row

#pragma unroll 4
    for (int j = 0; j < 12; j++) {
        int idx = base4 + 32 * j;
        float4 s = srow[idx];
        float4 v = vrow[idx];
        float d, p;
        d = s.x - xq.x; p  = __fdividef(d * d, v.x);
        d = s.y - xq.y; p += __fdividef(d * d, v.y);
        d = s.z - xq.z; p += __fdividef(d * d, v.z);
        d = s.w - xq.w; p += __fdividef(d * d, v.w);
        // reduce within the 8-lane tile group
        p += __shfl_down_sync(0xffffffffu, p, 4);
        p += __shfl_down_sync(0xffffffffu, p, 2);
        p += __shfl_down_sync(0xffffffffu, p, 1);
        if ((lane & 7) == 0)
            s_part[lrow][h * 48 + (lane >> 3) + 4 * j] = p;
    }
    __syncthreads();

    const int ui = rbase >> 5;             // tile row
    if (t < 96)
        atomicAdd(&g_z[ui * 96 + t],
                  s_part[0][t] + s_part[1][t] + s_part[2][t] + s_part[3][t]);

    // ---- last-block tail ----
    __shared__ bool amLast;
    if (t == 0) {
        __threadfence();
        amLast = (atomicAdd(&g_count, 1u) == ZBLK - 1);
    }
    __syncthreads();
    if (!amLast) return;
    __threadfence();

    unsigned long long best = 0xFFFFFFFFFFFFFFFFULL;
#pragma unroll
    for (int k = 0; k < NUNITS / 256; k++) {
        int e = t + k * 256;
        unsigned u = __float_as_uint(g_z[e]);
        u = (u & 0x80000000u) ? ~u : (u | 0x80000000u);   // orderable bits
        best = min(best, ((unsigned long long)u << 32) | (unsigned)e);
    }
#pragma unroll
    for (int o = 16; o; o >>= 1)
        best = min(best, __shfl_down_sync(0xffffffffu, best, o));
    __shared__ unsigned long long wm[8];
    if (lane == 0) wm[w] = best;
    __syncthreads();

    __shared__ float sp[5];
    __shared__ int sbmu;
    __shared__ float snr, snl;
    if (t == 0) {
        best = wm[0];
#pragma unroll
        for (int i = 1; i < 8; i++) best = min(best, wm[i]);
        int bmu = (int)(best & 0xFFFFFFFFULL);
        float rr = radius[bmu], lb = lrr[bmu];
        float dm = 1.0f / (2.0f * rr * rr);
        sp[0] = (float)(bmu / NU);
        sp[1] = (float)(bmu % NU);
        sp[2] = rr;
        sp[3] = dm;
        sp[4] = -logf(1e-7f / lb) / dm;
        sbmu = bmu;
        float c = bmu_count[bmu * 10];
        snr = expf(-c / 15.0f);
        snl = expf(-c / 25.0f);
    }
    __syncthreads();
    const float bi = sp[0], bj = sp[1], rr = sp[2], dm = sp[3], cst = sp[4];
    const int bmu = sbmu;
    const float nr = snr, nl = snl;

#pragma unroll
    for (int k = 0; k < NUNITS / 256; k++) {
        int e = t + k * 256;
        int i = e / NU, jj = e - i * NU;
        float di = (float)i - bi;
        float dj = (float)jj - bj;
        float cart = sqrtf(di * di + dj * dj);
        float mod = (cart > rr) ? 0.0f : cart;
        g_fm[e] = lrr[e] * expf(-mod) * dm;
        float sig = 1.0f / (1.0f + expf(-cart / cst));
        g_va[e] = fminf(fmaxf(0.4f + sig, 0.0f), 1.0f);   // ALPHA-0.5 = 0.4
        out_rad[e] = fmaxf((e == bmu) ? nr : radius[e], 1e-5f);
        out_lr[e]  = fmaxf((e == bmu) ? nl : lrr[e], 1e-5f);
        g_z[e] = 0.0f;                      // reset for next replay
    }
    if (t == 0) {
        g_count = 0;
        __threadfence();
    }
}

// ---------------------------------------------------------------------------
// k_update: block = 4 full rows, contiguous reads (L2-resident) and writes.
// fm/va from precomputed tables, staged in SMEM (8-lane broadcast reads).
// ---------------------------------------------------------------------------
__global__ void __launch_bounds__(256) k_update(const float* __restrict__ som,
                                                const float* __restrict__ var,
                                                const float* __restrict__ x,
                                                float* __restrict__ out_som,
                                                float* __restrict__ out_var) {
    __shared__ float4 sx[32];
    __shared__ float s_fm[96], s_va[96];
    const int t = threadIdx.x;
    const int w = t >> 5, lane = t & 31;
    const int lrow = w >> 1, h = w & 1;
    const int rbase = blockIdx.x * 4;
    const int r = rbase + lrow;
    const int ui = rbase >> 5;

    if (t < 32)
        sx[t] = ((const float4*)x)[((rbase & 31) + (t >> 3)) * 8 + (t & 7)];
    else if (t >= 64 && t < 160)
        s_fm[t - 64] = g_fm[ui * 96 + (t - 64)];
    else if (t >= 160)
        s_va[t - 160] = g_va[ui * 96 + (t - 160)];
    __syncthreads();

    const float4* srow = (const float4*)(som + (size_t)r * SHAPE);
    const float4* vrow = (const float4*)(var + (size_t)r * SHAPE);
    float4* osrow = (float4*)(out_som + (size_t)r * SHAPE);
    float4* ovrow = (float4*)(out_var + (size_t)r * SHAPE);
    const float4 xq = sx[(lrow << 3) | (lane & 7)];
    const int base4 = h * 384 + lane;

#pragma unroll 4
    for (int j = 0; j < 12; j++) {
        int idx = base4 + 32 * j;
        int T = h * 48 + (lane >> 3) + 4 * j;    // tile within row
        float fm = s_fm[T];
        float va = s_va[T];
        float iva = 1.0f - va;
        float4 s = __ldlu(&srow[idx]);
        float4 v = __ldlu(&vrow[idx]);
        float4 os, ov;
#define UPD1(SS, XX, VV, OS, OV)                               \
        {                                                      \
            float ns = SS + fm * (XX - SS);                    \
            float dd = XX - ns;                                \
            OV = va * VV + iva * dd * dd;                      \
            OS = fminf(fmaxf(ns, 0.0f), 1.0f);                 \
        }
        UPD1(s.x, xq.x, v.x, os.x, ov.x)
        UPD1(s.y, xq.y, v.y, os.y, ov.y)
        UPD1(s.z, xq.z, v.z, os.z, ov.z)
        UPD1(s.w, xq.w, v.w, os.w, ov.w)
#undef UPD1
        __stcs(&osrow[idx], os);
        __stcs(&ovrow[idx], ov);
    }
}

extern "C" void kernel_launch(void* const* d_in, const int* in_sizes, int n_in,
                              void* d_out, int out_size) {
    const float* x      = (const float*)d_in[0];
    const float* som    = (const float*)d_in[1];
    const float* var    = (const float*)d_in[2];
    const float* radius = (const float*)d_in[3];
    const float* lr     = (const float*)d_in[4];
    const float* bmu    = (const float*)d_in[5];

    float* out      = (float*)d_out;
    float* out_som  = out;
    float* out_var  = out + (size_t)NELEM;
    float* out_rad  = out + 2ULL * NELEM;
    float* out_lr   = out + 2ULL * NELEM + NUNITS;

    k_z<<<ZBLK, 256>>>(som, var, x, radius, lr, bmu, out_rad, out_lr);
    k_update<<<ZBLK, 256>>>(som, var, x, out_som, out_var);
}

// round 12
// speedup vs baseline: 1.9445x; 1.9445x over previous
#include <cuda_runtime.h>

#define NU 96
#define IMG 32
#define SHAPE 3072                 // NU*IMG
#define NUNITS 9216                // NU*NU
#define NELEM (SHAPE * SHAPE)
#define NBLK (NUNITS / 2)          // 4608 blocks, 2 tiles each

// Scratch (no allocations). g_zmin zero-init = identity for inverted-key max;
// tail resets it each launch -> stateless across graph replays.
__device__ unsigned long long g_zmin[NU];   // per-ui inverted best key
__device__ float g_params[5];               // bi, bj, r, dm, constant
__device__ int   g_bmu;
__device__ unsigned g_count;

// ---------------------------------------------------------------------------
// k_z: one 128-thread block per PAIR of adjacent tiles. 8 front-batched
// LDG.128 per thread. Block best key -> inverted atomicMax into g_zmin[ui].
// Tiny last-block tail: reduce 96 keys, BMU scalars, reset scratch.
// ---------------------------------------------------------------------------
__global__ void __launch_bounds__(128) k_z(const float* __restrict__ som,
                                           const float* __restrict__ var,
                                           const float* __restrict__ x,
                                           const float* __restrict__ radius,
                                           const float* __restrict__ lr) {
    const int u0 = blockIdx.x * 2;        // even unit; u1 = u0+1 same ui
    const int ui = u0 / NU, uj0 = u0 - ui * NU;
    const int t = threadIdx.x;
    const int rowA = t >> 3;              // 0..15
    const int col  = (t & 7) * 4;         // float4 column

    const float* sb = som + (size_t)ui * IMG * SHAPE + uj0 * IMG;
    const float* vb = var + (size_t)ui * IMG * SHAPE + uj0 * IMG;

    const size_t oA = (size_t)rowA * SHAPE + col;
    const size_t oB = (size_t)(rowA + 16) * SHAPE + col;

    // 8 independent som/var loads batched up front (tiles 0 and 1)
    float4 sa0 = *(const float4*)(sb + oA);
    float4 sb0 = *(const float4*)(sb + oB);
    float4 sa1 = *(const float4*)(sb + oA + IMG);
    float4 sb1 = *(const float4*)(sb + oB + IMG);
    float4 va0 = *(const float4*)(vb + oA);
    float4 vb0 = *(const float4*)(vb + oB);
    float4 va1 = *(const float4*)(vb + oA + IMG);
    float4 vb1 = *(const float4*)(vb + oB + IMG);
    float4 x0 = *(const float4*)(x + rowA * IMG + col);
    float4 x1 = *(const float4*)(x + (rowA + 16) * IMG + col);

    float d;
    float acc0 = 0.0f, acc1 = 0.0f;
    d = sa0.x - x0.x; acc0 += __fdividef(d * d, va0.x);
    d = sa0.y - x0.y; acc0 += __fdividef(d * d, va0.y);
    d = sa0.z - x0.z; acc0 += __fdividef(d * d, va0.z);
    d = sa0.w - x0.w; acc0 += __fdividef(d * d, va0.w);
    d = sb0.x - x1.x; acc0 += __fdividef(d * d, vb0.x);
    d = sb0.y - x1.y; acc0 += __fdividef(d * d, vb0.y);
    d = sb0.z - x1.z; acc0 += __fdividef(d * d, vb0.z);
    d = sb0.w - x1.w; acc0 += __fdividef(d * d, vb0.w);
    d = sa1.x - x0.x; acc1 += __fdividef(d * d, va1.x);
    d = sa1.y - x0.y; acc1 += __fdividef(d * d, va1.y);
    d = sa1.z - x0.z; acc1 += __fdividef(d * d, va1.z);
    d = sa1.w - x0.w; acc1 += __fdividef(d * d, va1.w);
    d = sb1.x - x1.x; acc1 += __fdividef(d * d, vb1.x);
    d = sb1.y - x1.y; acc1 += __fdividef(d * d, vb1.y);
    d = sb1.z - x1.z; acc1 += __fdividef(d * d, vb1.z);
    d = sb1.w - x1.w; acc1 += __fdividef(d * d, vb1.w);

#pragma unroll
    for (int o = 16; o; o >>= 1) {
        acc0 += __shfl_down_sync(0xffffffffu, acc0, o);
        acc1 += __shfl_down_sync(0xffffffffu, acc1, o);
    }
    __shared__ float ws0[4], ws1[4];
    if ((t & 31) == 0) { ws0[t >> 5] = acc0; ws1[t >> 5] = acc1; }
    __syncthreads();
    if (t == 0) {
        float z0 = ws0[0] + ws0[1] + ws0[2] + ws0[3];
        float z1 = ws1[0] + ws1[1] + ws1[2] + ws1[3];
        unsigned a = __float_as_uint(z0);
        a = (a & 0x80000000u) ? ~a : (a | 0x80000000u);   // orderable bits
        unsigned b = __float_as_uint(z1);
        b = (b & 0x80000000u) ? ~b : (b | 0x80000000u);
        unsigned long long k0 = ((unsigned long long)a << 32) | (unsigned)u0;
        unsigned long long k1 = ((unsigned long long)b << 32) | (unsigned)(u0 + 1);
        // inverted key: max over ~key == min over key; 0 is the identity
        atomicMax(&g_zmin[ui], ~min(k0, k1));
    }

    // ---- tiny last-block tail: 96-key reduce + BMU scalars + reset ----
    __shared__ bool amLast;
    if (t == 0) {
        __threadfence();
        amLast = (atomicAdd(&g_count, 1u) == NBLK - 1);
    }
    __syncthreads();
    if (!amLast) return;
    __threadfence();

    unsigned long long inv = 0ULL;
    if (t < NU) inv = g_zmin[t];
#pragma unroll
    for (int o = 16; o; o >>= 1)
        inv = max(inv, __shfl_down_sync(0xffffffffu, inv, o));
    __shared__ unsigned long long wm[4];
    if ((t & 31) == 0) wm[t >> 5] = inv;
    __syncthreads();
    if (t == 0) {
        inv = max(max(wm[0], wm[1]), max(wm[2], wm[3]));
        unsigned long long best = ~inv;
        int bmu = (int)(best & 0xFFFFFFFFULL);
        float r   = radius[bmu];
        float lrb = lr[bmu];
        float dm  = 1.0f / (2.0f * r * r);
        g_params[0] = (float)(bmu / NU);
        g_params[1] = (float)(bmu % NU);
        g_params[2] = r;
        g_params[3] = dm;
        g_params[4] = -logf(1e-7f / lrb) / dm;
        g_bmu = bmu;
        g_count = 0;                        // reset for next graph replay
    }
    if (t < NU) g_zmin[t] = 0ULL;           // reset identity
    if (t == 0) __threadfence();
}

// ---------------------------------------------------------------------------
// k_update: one 128-thread block per tile pair (R9-proven). 8 batched __ldlu
// reads, __stcs streaming stores. Blocks 0..71 also emit radius/lr outputs.
// ---------------------------------------------------------------------------
__global__ void __launch_bounds__(128) k_update(const float* __restrict__ som,
                                                const float* __restrict__ var,
                                                const float* __restrict__ x,
                                                const float* __restrict__ lr,
                                                const float* __restrict__ radius,
                                                const float* __restrict__ bmu_count,
                                                float* __restrict__ out_som,
                                                float* __restrict__ out_var,
                                                float* __restrict__ out_rad,
                                                float* __restrict__ out_lr) {
    const int u0 = blockIdx.x * 2;
    const int ui = u0 / NU, uj0 = u0 - ui * NU;
    const int t = threadIdx.x;

    const float bi = g_params[0], bj = g_params[1];
    const float r = g_params[2], dm = g_params[3], cst = g_params[4];
    const int bmu = g_bmu;

    // Side job: radius / learning-rate outputs (blocks 0..71)
    if (blockIdx.x < NUNITS / 128) {
        int e = blockIdx.x * 128 + t;
        float c  = bmu_count[bmu * 10];
        float nr = expf(-c / 15.0f);
        float nl = expf(-c / 25.0f);
        out_rad[e] = fmaxf((e == bmu) ? nr : radius[e], 1e-5f);
        out_lr[e]  = fmaxf((e == bmu) ? nl : lr[e], 1e-5f);
    }

    const int rowA = t >> 3;
    const int col  = (t & 7) * 4;
    const size_t base = (size_t)ui * IMG * SHAPE + uj0 * IMG;
    const size_t oA = base + (size_t)rowA * SHAPE + col;
    const size_t oB = base + (size_t)(rowA + 16) * SHAPE + col;

    // 8 batched reads (L2-resident from k_z; last-use hint)
    float4 sa0 = __ldlu((const float4*)(som + oA));
    float4 sb0 = __ldlu((const float4*)(som + oB));
    float4 sa1 = __ldlu((const float4*)(som + oA + IMG));
    float4 sb1 = __ldlu((const float4*)(som + oB + IMG));
    float4 va0 = __ldlu((const float4*)(var + oA));
    float4 vb0 = __ldlu((const float4*)(var + oB));
    float4 va1 = __ldlu((const float4*)(var + oA + IMG));
    float4 vb1 = __ldlu((const float4*)(var + oB + IMG));
    float4 x0 = *(const float4*)(x + rowA * IMG + col);
    float4 x1 = *(const float4*)(x + (rowA + 16) * IMG + col);

    // Per-tile scalars (redundant per thread)
    const float di = (float)ui - bi;
    const float dj0 = (float)uj0 - bj;
    const float dj1 = (float)(uj0 + 1) - bj;
    float cart0 = sqrtf(di * di + dj0 * dj0);
    float cart1 = sqrtf(di * di + dj1 * dj1);
    float fm0 = lr[u0]     * expf(-((cart0 > r) ? 0.0f : cart0)) * dm;
    float fm1 = lr[u0 + 1] * expf(-((cart1 > r) ? 0.0f : cart1)) * dm;
    float vaA = fminf(fmaxf(0.4f + 1.0f / (1.0f + expf(-cart0 / cst)), 0.0f), 1.0f);
    float vaB = fminf(fmaxf(0.4f + 1.0f / (1.0f + expf(-cart1 / cst)), 0.0f), 1.0f);
    float ivA = 1.0f - vaA, ivB = 1.0f - vaB;

    float4 os, ov;
#define UPD1(S, X, V, FM, VA, IVA, OS, OV)                     \
    {                                                          \
        float ns = S + FM * (X - S);                           \
        float dd = X - ns;                                     \
        OV = VA * V + IVA * dd * dd;                           \
        OS = fminf(fmaxf(ns, 0.0f), 1.0f);                     \
    }
#define UPD4(SV, XV, VV, FM, VA, IVA, OUTS, OUTV, OFF)         \
    UPD1(SV.x, XV.x, VV.x, FM, VA, IVA, os.x, ov.x)            \
    UPD1(SV.y, XV.y, VV.y, FM, VA, IVA, os.y, ov.y)            \
    UPD1(SV.z, XV.z, VV.z, FM, VA, IVA, os.z, ov.z)            \
    UPD1(SV.w, XV.w, VV.w, FM, VA, IVA, os.w, ov.w)            \
    __stcs((float4*)(OUTS + OFF), os);                         \
    __stcs((float4*)(OUTV + OFF), ov);

    UPD4(sa0, x0, va0, fm0, vaA, ivA, out_som, out_var, oA)
    UPD4(sb0, x1, vb0, fm0, vaA, ivA, out_som, out_var, oB)
    UPD4(sa1, x0, va1, fm1, vaB, ivB, out_som, out_var, oA + IMG)
    UPD4(sb1, x1, vb1, fm1, vaB, ivB, out_som, out_var, oB + IMG)
#undef UPD4
#undef UPD1
}

extern "C" void kernel_launch(void* const* d_in, const int* in_sizes, int n_in,
                              void* d_out, int out_size) {
    const float* x      = (const float*)d_in[0];
    const float* som    = (const float*)d_in[1];
    const float* var    = (const float*)d_in[2];
    const float* radius = (const float*)d_in[3];
    const float* lr     = (const float*)d_in[4];
    const float* bmu    = (const float*)d_in[5];

    float* out      = (float*)d_out;
    float* out_som  = out;
    float* out_var  = out + (size_t)NELEM;
    float* out_rad  = out + 2ULL * NELEM;
    float* out_lr   = out + 2ULL * NELEM + NUNITS;

    k_z<<<NBLK, 128>>>(som, var, x, radius, lr);
    k_update<<<NBLK, 128>>>(som, var, x, lr, radius, bmu,
                            out_som, out_var, out_rad, out_lr);
}

// round 14
// speedup vs baseline: 1.9834x; 1.0200x over previous
#include <cuda_runtime.h>

#define NU 96
#define IMG 32
#define SHAPE 3072                 // NU*IMG
#define NUNITS 9216                // NU*NU
#define NELEM (SHAPE * SHAPE)
#define NBLK (NUNITS / 2)          // 4608 blocks, 2 tiles each

// Scratch (no allocations). g_zmin zero-init = identity for inverted-key max;
// tail resets it each launch -> stateless across graph replays.
__device__ unsigned long long g_zmin[NU];   // per-ui inverted best key
__device__ float g_params[5];               // bi, bj, r, dm, constant
__device__ int   g_bmu;
__device__ unsigned g_count;

// ---------------------------------------------------------------------------
// k_z: one 128-thread block per PAIR of adjacent tiles. 8 front-batched
// LDG.128 per thread. Block best key -> inverted atomicMax into g_zmin[ui].
// Tiny last-block tail: reduce 96 keys, BMU scalars, reset scratch.
// ---------------------------------------------------------------------------
__global__ void __launch_bounds__(128) k_z(const float* __restrict__ som,
                                           const float* __restrict__ var,
                                           const float* __restrict__ x,
                                           const float* __restrict__ radius,
                                           const float* __restrict__ lr) {
    const int u0 = blockIdx.x * 2;        // even unit; u1 = u0+1 same ui
    const int ui = u0 / NU, uj0 = u0 - ui * NU;
    const int t = threadIdx.x;
    const int rowA = t >> 3;              // 0..15
    const int col  = (t & 7) * 4;         // float4 column

    const float* sb = som + (size_t)ui * IMG * SHAPE + uj0 * IMG;
    const float* vb = var + (size_t)ui * IMG * SHAPE + uj0 * IMG;

    const size_t oA = (size_t)rowA * SHAPE + col;
    const size_t oB = (size_t)(rowA + 16) * SHAPE + col;

    // 8 independent som/var loads batched up front (tiles 0 and 1)
    float4 sa0 = *(const float4*)(sb + oA);
    float4 sb0 = *(const float4*)(sb + oB);
    float4 sa1 = *(const float4*)(sb + oA + IMG);
    float4 sb1 = *(const float4*)(sb + oB + IMG);
    float4 va0 = *(const float4*)(vb + oA);
    float4 vb0 = *(const float4*)(vb + oB);
    float4 va1 = *(const float4*)(vb + oA + IMG);
    float4 vb1 = *(const float4*)(vb + oB + IMG);
    float4 x0 = *(const float4*)(x + rowA * IMG + col);
    float4 x1 = *(const float4*)(x + (rowA + 16) * IMG + col);

    float d;
    float acc0 = 0.0f, acc1 = 0.0f;
    d = sa0.x - x0.x; acc0 += __fdividef(d * d, va0.x);
    d = sa0.y - x0.y; acc0 += __fdividef(d * d, va0.y);
    d = sa0.z - x0.z; acc0 += __fdividef(d * d, va0.z);
    d = sa0.w - x0.w; acc0 += __fdividef(d * d, va0.w);
    d = sb0.x - x1.x; acc0 += __fdividef(d * d, vb0.x);
    d = sb0.y - x1.y; acc0 += __fdividef(d * d, vb0.y);
    d = sb0.z - x1.z; acc0 += __fdividef(d * d, vb0.z);
    d = sb0.w - x1.w; acc0 += __fdividef(d * d, vb0.w);
    d = sa1.x - x0.x; acc1 += __fdividef(d * d, va1.x);
    d = sa1.y - x0.y; acc1 += __fdividef(d * d, va1.y);
    d = sa1.z - x0.z; acc1 += __fdividef(d * d, va1.z);
    d = sa1.w - x0.w; acc1 += __fdividef(d * d, va1.w);
    d = sb1.x - x1.x; acc1 += __fdividef(d * d, vb1.x);
    d = sb1.y - x1.y; acc1 += __fdividef(d * d, vb1.y);
    d = sb1.z - x1.z; acc1 += __fdividef(d * d, vb1.z);
    d = sb1.w - x1.w; acc1 += __fdividef(d * d, vb1.w);

#pragma unroll
    for (int o = 16; o; o >>= 1) {
        acc0 += __shfl_down_sync(0xffffffffu, acc0, o);
        acc1 += __shfl_down_sync(0xffffffffu, acc1, o);
    }
    __shared__ float ws0[4], ws1[4];
    if ((t & 31) == 0) { ws0[t >> 5] = acc0; ws1[t >> 5] = acc1; }
    __syncthreads();
    if (t == 0) {
        float z0 = ws0[0] + ws0[1] + ws0[2] + ws0[3];
        float z1 = ws1[0] + ws1[1] + ws1[2] + ws1[3];
        unsigned a = __float_as_uint(z0);
        a = (a & 0x80000000u) ? ~a : (a | 0x80000000u);   // orderable bits
        unsigned b = __float_as_uint(z1);
        b = (b & 0x80000000u) ? ~b : (b | 0x80000000u);
        unsigned long long k0 = ((unsigned long long)a << 32) | (unsigned)u0;
        unsigned long long k1 = ((unsigned long long)b << 32) | (unsigned)(u0 + 1);
        // inverted key: max over ~key == min over key; 0 is the identity
        atomicMax(&g_zmin[ui], ~min(k0, k1));
    }

    // ---- tiny last-block tail: 96-key reduce + BMU scalars + reset ----
    __shared__ bool amLast;
    if (t == 0) {
        __threadfence();
        amLast = (atomicAdd(&g_count, 1u) == NBLK - 1);
    }
    __syncthreads();
    if (!amLast) return;
    __threadfence();

    unsigned long long inv = 0ULL;
    if (t < NU) inv = g_zmin[t];
#pragma unroll
    for (int o = 16; o; o >>= 1)
        inv = max(inv, __shfl_down_sync(0xffffffffu, inv, o));
    __shared__ unsigned long long wm[4];
    if ((t & 31) == 0) wm[t >> 5] = inv;
    __syncthreads();
    if (t == 0) {
        inv = max(max(wm[0], wm[1]), max(wm[2], wm[3]));
        unsigned long long best = ~inv;
        int bmu = (int)(best & 0xFFFFFFFFULL);
        float r   = radius[bmu];
        float lrb = lr[bmu];
        float dm  = 1.0f / (2.0f * r * r);
        g_params[0] = (float)(bmu / NU);
        g_params[1] = (float)(bmu % NU);
        g_params[2] = r;
        g_params[3] = dm;
        g_params[4] = -logf(1e-7f / lrb) / dm;
        g_bmu = bmu;
        g_count = 0;                        // reset for next graph replay
    }
    if (t < NU) g_zmin[t] = 0ULL;           // reset identity
    if (t == 0) __threadfence();
}

// ---------------------------------------------------------------------------
// k_update (PDL secondary): issue ALL data loads first (independent of the
// argmin), then cudaGridDependencySynchronize(), then read BMU params and
// compute. Overlaps this kernel's launch + load latency with k_z's drain.
// ---------------------------------------------------------------------------
__global__ void __launch_bounds__(128) k_update(const float* __restrict__ som,
                                                const float* __restrict__ var,
                                                const float* __restrict__ x,
                                                const float* __restrict__ lr,
                                                const float* __restrict__ radius,
                                                const float* __restrict__ bmu_count,
                                                float* __restrict__ out_som,
                                                float* __restrict__ out_var,
                                                float* __restrict__ out_rad,
                                                float* __restrict__ out_lr) {
    const int u0 = blockIdx.x * 2;
    const int ui = u0 / NU, uj0 = u0 - ui * NU;
    const int t = threadIdx.x;

    const int rowA = t >> 3;
    const int col  = (t & 7) * 4;
    const size_t base = (size_t)ui * IMG * SHAPE + uj0 * IMG;
    const size_t oA = base + (size_t)rowA * SHAPE + col;
    const size_t oB = base + (size_t)(rowA + 16) * SHAPE + col;

    // ---- preamble: every load that does NOT depend on the argmin ----
    float4 sa0 = __ldlu((const float4*)(som + oA));
    float4 sb0 = __ldlu((const float4*)(som + oB));
    float4 sa1 = __ldlu((const float4*)(som + oA + IMG));
    float4 sb1 = __ldlu((const float4*)(som + oB + IMG));
    float4 va0 = __ldlu((const float4*)(var + oA));
    float4 vb0 = __ldlu((const float4*)(var + oB));
    float4 va1 = __ldlu((const float4*)(var + oA + IMG));
    float4 vb1 = __ldlu((const float4*)(var + oB + IMG));
    float4 x0 = *(const float4*)(x + rowA * IMG + col);
    float4 x1 = *(const float4*)(x + (rowA + 16) * IMG + col);
    float lr0 = lr[u0];
    float lr1 = lr[u0 + 1];

    // ---- wait for k_z grid (params + bmu now visible) ----
    cudaGridDependencySynchronize();

    const float bi = g_params[0], bj = g_params[1];
    const float r = g_params[2], dm = g_params[3], cst = g_params[4];
    const int bmu = g_bmu;

    // Side job: radius / learning-rate outputs (blocks 0..71)
    if (blockIdx.x < NUNITS / 128) {
        int e = blockIdx.x * 128 + t;
        float c  = bmu_count[bmu * 10];
        float nr = expf(-c / 15.0f);
        float nl = expf(-c / 25.0f);
        out_rad[e] = fmaxf((e == bmu) ? nr : radius[e], 1e-5f);
        out_lr[e]  = fmaxf((e == bmu) ? nl : lr[e], 1e-5f);
    }

    // Per-tile scalars (redundant per thread)
    const float di = (float)ui - bi;
    const float dj0 = (float)uj0 - bj;
    const float dj1 = (float)(uj0 + 1) - bj;
    float cart0 = sqrtf(di * di + dj0 * dj0);
    float cart1 = sqrtf(di * di + dj1 * dj1);
    float fm0 = lr0 * expf(-((cart0 > r) ? 0.0f : cart0)) * dm;
    float fm1 = lr1 * expf(-((cart1 > r) ? 0.0f : cart1)) * dm;
    float vaA = fminf(fmaxf(0.4f + 1.0f / (1.0f + expf(-cart0 / cst)), 0.0f), 1.0f);
    float vaB = fminf(fmaxf(0.4f + 1.0f / (1.0f + expf(-cart1 / cst)), 0.0f), 1.0f);
    float ivA = 1.0f - vaA, ivB = 1.0f - vaB;

    float4 os, ov;
#define UPD1(S, X, V, FM, VA, IVA, OS, OV)                     \
    {                                                          \
        float ns = S + FM * (X - S);                           \
        float dd = X - ns;                                     \
        OV = VA * V + IVA * dd * dd;                           \
        OS = fminf(fmaxf(ns, 0.0f), 1.0f);                     \
    }
#define UPD4(SV, XV, VV, FM, VA, IVA, OUTS, OUTV, OFF)         \
    UPD1(SV.x, XV.x, VV.x, FM, VA, IVA, os.x, ov.x)            \
    UPD1(SV.y, XV.y, VV.y, FM, VA, IVA, os.y, ov.y)            \
    UPD1(SV.z, XV.z, VV.z, FM, VA, IVA, os.z, ov.z)            \
    UPD1(SV.w, XV.w, VV.w, FM, VA, IVA, os.w, ov.w)            \
    __stcs((float4*)(OUTS + OFF), os);                         \
    __stcs((float4*)(OUTV + OFF), ov);

    UPD4(sa0, x0, va0, fm0, vaA, ivA, out_som, out_var, oA)
    UPD4(sb0, x1, vb0, fm0, vaA, ivA, out_som, out_var, oB)
    UPD4(sa1, x0, va1, fm1, vaB, ivB, out_som, out_var, oA + IMG)
    UPD4(sb1, x1, vb1, fm1, vaB, ivB, out_som, out_var, oB + IMG)
#undef UPD4
#undef UPD1
}

extern "C" void kernel_launch(void* const* d_in, const int* in_sizes, int n_in,
                              void* d_out, int out_size) {
    const float* x      = (const float*)d_in[0];
    const float* som    = (const float*)d_in[1];
    const float* var    = (const float*)d_in[2];
    const float* radius = (const float*)d_in[3];
    const float* lr     = (const float*)d_in[4];
    const float* bmu    = (const float*)d_in[5];

    float* out      = (float*)d_out;
    float* out_som  = out;
    float* out_var  = out + (size_t)NELEM;
    float* out_rad  = out + 2ULL * NELEM;
    float* out_lr   = out + 2ULL * NELEM + NUNITS;

    k_z<<<NBLK, 128>>>(som, var, x, radius, lr);

    // PDL secondary: may begin launching while k_z drains; ordering enforced
    // in-kernel by cudaGridDependencySynchronize().
    cudaLaunchConfig_t cfg = {};
    cfg.gridDim = dim3(NBLK);
    cfg.blockDim = dim3(128);
    cfg.dynamicSmemBytes = 0;
    cfg.stream = 0;                        // same (capture) stream as <<<>>>
    cudaLaunchAttribute attr[1];
    attr[0].id = cudaLaunchAttributeProgrammaticStreamSerialization;
    attr[0].val.programmaticStreamSerializationAllowed = 1;
    cfg.attrs = attr;
    cfg.numAttrs = 1;
    cudaLaunchKernelEx(&cfg, k_update, som, var, x, lr, radius, bmu,
                       out_som, out_var, out_rad, out_lr);
}